// round 17
// baseline (speedup 1.0000x reference)
#include <cuda_runtime.h>
#include <cuda_fp16.h>

#define N_NODES 20000
#define N_EDGES 200000
#define EDIM 128
#define CE 256                 // C * E_DIM
#define MAXD 64                // bin capacity per node (deg ~ Poisson(10): P(>64) ~ 1e-30)
#define NHALF2 (N_NODES * CE / 2)   // 2,560,000 half2
#define SCATTER_THREADS (N_EDGES / 4)
#define CONV_BLOCKS 5120       // 5120*256 = 1,310,720 threads = NHALF2/2 float4s

// Scratch in __device__ globals (zero-initialized at load; g_cnt invariant:
// zero at entry of every kernel_launch call, restored by node_kernel).
__device__ int     g_cnt[N_NODES];           // packed: lo16 = n_left, hi16 = n_right
__device__ int     g_meta[N_NODES * MAXD];   // src ids; left fills from front, right from back
__device__ __align__(16) __half2 g_feat_h[NHALF2];  // fp16 shadow (10.25 MB, L2-resident)
__device__ float   g_scale[2][EDIM];
__device__ float   g_bias[2][EDIM];

// One launch: sigmoid tables (block 0), dual-end bin scatter (first 50K
// threads), f32->fp16 shadow build (each thread converts exactly one float4).
__global__ void __launch_bounds__(256) scatter_kernel(
    const float* __restrict__ feat,
    const int* __restrict__ src, const int* __restrict__ dst,
    const int* __restrict__ pos,
    const float* __restrict__ dl, const float* __restrict__ dr,
    const float* __restrict__ lb, const float* __restrict__ rb)
{
    if (blockIdx.x == 0 && threadIdx.x < EDIM) {
        int e = threadIdx.x;
        g_scale[0][e] = 1.0f / (1.0f + __expf(-dl[e]));
        g_scale[1][e] = 1.0f / (1.0f + __expf(-dr[e]));
        g_bias[0][e]  = lb[e];
        g_bias[1][e]  = rb[e];
    }

    int t = blockIdx.x * blockDim.x + threadIdx.x;

    if (t < SCATTER_THREADS) {     // N_EDGES % 4 == 0, full int4 loads are safe
        int e0 = t * 4;
        int4 s4 = *reinterpret_cast<const int4*>(src + e0);
        int4 d4 = *reinterpret_cast<const int4*>(dst + e0);
        int4 p4 = *reinterpret_cast<const int4*>(pos + e0);

        #pragma unroll
        for (int k = 0; k < 4; k++) {
            int s = (&s4.x)[k];
            int d = (&d4.x)[k];
            bool right = ((&p4.x)[k] != 0);
            int old = atomicAdd(&g_cnt[d], right ? 0x10000 : 1);
            int slot = right ? (MAXD - 1 - (old >> 16)) : (old & 0xFFFF);
            g_meta[d * MAXD + slot] = s;
        }
    }

    // fp16 shadow: exactly one float4 -> 2 half2 (8B store) per thread
    if (t < NHALF2 / 2) {
        float4 f = reinterpret_cast<const float4*>(feat)[t];
        __half2 h0 = __floats2half2_rn(f.x, f.y);
        __half2 h1 = __floats2half2_rn(f.z, f.w);
        uint2 u;
        u.x = *reinterpret_cast<unsigned*>(&h0);
        u.y = *reinterpret_cast<unsigned*>(&h1);
        reinterpret_cast<uint2*>(g_feat_h)[t] = u;
    }
}

// Accumulate one uint4 (4 half2 = 8 fp16 values) into 4 half2 accumulators.
#define ACC_U4(A, H) do { \
    (A)[0] = __hadd2((A)[0], *reinterpret_cast<const __half2*>(&(H).x)); \
    (A)[1] = __hadd2((A)[1], *reinterpret_cast<const __half2*>(&(H).y)); \
    (A)[2] = __hadd2((A)[2], *reinterpret_cast<const __half2*>(&(H).z)); \
    (A)[3] = __hadd2((A)[3], *reinterpret_cast<const __half2*>(&(H).w)); } while (0)

// Gather rows for slots [lo, hi) stepping slots by +1 (left) with a 4-deep
// ladder; meta via scalar __ldg (warp-uniform), rows via lane-owned LDG.128.
__device__ __forceinline__ void gather_range(__half2* a, const int* mp,
                                             const uint4* fb, int lo, int hi) {
    int i = lo;
    for (; i + 4 <= hi; i += 4) {
        int m0 = __ldg(mp + i),     m1 = __ldg(mp + i + 1);
        int m2 = __ldg(mp + i + 2), m3 = __ldg(mp + i + 3);
        uint4 h0 = fb[(unsigned)m0 * 32];
        uint4 h1 = fb[(unsigned)m1 * 32];
        uint4 h2 = fb[(unsigned)m2 * 32];
        uint4 h3 = fb[(unsigned)m3 * 32];
        ACC_U4(a, h0); ACC_U4(a, h1); ACC_U4(a, h2); ACC_U4(a, h3);
    }
    if (i + 2 <= hi) {
        int m0 = __ldg(mp + i), m1 = __ldg(mp + i + 1);
        uint4 h0 = fb[(unsigned)m0 * 32];
        uint4 h1 = fb[(unsigned)m1 * 32];
        ACC_U4(a, h0); ACC_U4(a, h1);
        i += 2;
    }
    if (i < hi) {
        uint4 h0 = fb[(unsigned)__ldg(mp + i) * 32];
        ACC_U4(a, h0);
    }
}

// ONE NODE PER 64-THREAD BLOCK, BALANCED WARP SPLIT:
//   The node's edges form one logical list: left edges at slots [0, nl),
//   right edges at slots [MAXD-nr, MAXD) (logical index i>=nl -> slot
//   MAXD-1-(i-nl) .. i.e. right run occupies a contiguous slot range).
//   Warp w takes logical range [w*half, min(deg,(w+1)*half)), half=(deg+1)/2
//   — critical warp does ceil(deg/2) (~5.2) edges instead of max(nl,nr)
//   (~6.1). Each warp runs two select-free sub-loops (left part -> accL,
//   right part -> accR); lane owns 16B of the 512B fp16 row (LDG.128/edge).
// 2KB smem exchange; all 64 threads finalize 4 floats in fp32:
//   out = (accL*sc0 + accR*sc1 + nl*b0 + nr*b1) / max(deg,1).
__global__ void __launch_bounds__(64) node_kernel(float* __restrict__ out) {
    __shared__ uint4 s_acc[2][2][32];       // [warp][side][lane] -> 4 half2

    unsigned node = blockIdx.x;             // grid is exactly N_NODES blocks
    unsigned tidx = threadIdx.x;            // 0..63
    unsigned w    = tidx >> 5;
    unsigned lane = tidx & 31u;

    int cnt = g_cnt[node];
    int nl  = cnt & 0xFFFF;
    int nr  = cnt >> 16;
    int deg = nl + nr;

    const int* mp = &g_meta[node * MAXD];
    const uint4* fb = reinterpret_cast<const uint4*>(g_feat_h) + lane;
    // row stride: CE/2 = 128 half2 = 32 uint4

    int half  = (deg + 1) >> 1;
    int begin = (int)w * half;
    int end   = min(deg, begin + half);

    __half2 aL[4], aR[4];
    aL[0] = aL[1] = aL[2] = aL[3] = __floats2half2_rn(0.f, 0.f);
    aR[0] = aR[1] = aR[2] = aR[3] = aL[0];

    // left portion of my range: logical i in [begin, min(end, nl)), slot = i
    int endL = min(end, nl);
    if (begin < endL) gather_range(aL, mp, fb, begin, endL);

    // right portion: logical i in [max(begin,nl), end),
    // cursor c = i - nl in [c0, c1), slot = MAXD-1-c -> contiguous slot range
    // [MAXD-c1, MAXD-c0) walked ascending (order irrelevant for a sum).
    int c0 = max(begin, nl) - nl;
    int c1 = end - nl;
    if (c1 > c0) gather_range(aR, mp, fb, MAXD - c1, MAXD - c0);

    s_acc[w][0][lane] = *reinterpret_cast<const uint4*>(aL);
    s_acc[w][1][lane] = *reinterpret_cast<const uint4*>(aR);
    __syncthreads();
    if (tidx == 0) g_cnt[node] = 0;         // restore invariant for next replay

    // Epilogue: thread t finalizes floats [4t, 4t+4). Its half2 pair lives at
    // s_acc[w][side][t>>1] words [2*(t&1), 2*(t&1)+1]; combine warps in fp32.
    unsigned off = tidx * 4u;               // float offset 0..252
    unsigned e   = off & (EDIM - 1);        // scale/bias repeat per channel
    unsigned widx = 2 * (tidx & 1);
    unsigned lidx = tidx >> 1;

    const unsigned* p0L = reinterpret_cast<const unsigned*>(&s_acc[0][0][lidx]) + widx;
    const unsigned* p1L = reinterpret_cast<const unsigned*>(&s_acc[1][0][lidx]) + widx;
    const unsigned* p0R = reinterpret_cast<const unsigned*>(&s_acc[0][1][lidx]) + widx;
    const unsigned* p1R = reinterpret_cast<const unsigned*>(&s_acc[1][1][lidx]) + widx;

    float2 l01 = __half22float2(*reinterpret_cast<const __half2*>(p0L));
    float2 l23 = __half22float2(*reinterpret_cast<const __half2*>(p0L + 1));
    float2 m01 = __half22float2(*reinterpret_cast<const __half2*>(p1L));
    float2 m23 = __half22float2(*reinterpret_cast<const __half2*>(p1L + 1));
    l01.x += m01.x; l01.y += m01.y; l23.x += m23.x; l23.y += m23.y;

    float2 r01 = __half22float2(*reinterpret_cast<const __half2*>(p0R));
    float2 r23 = __half22float2(*reinterpret_cast<const __half2*>(p0R + 1));
    float2 n01 = __half22float2(*reinterpret_cast<const __half2*>(p1R));
    float2 n23 = __half22float2(*reinterpret_cast<const __half2*>(p1R + 1));
    r01.x += n01.x; r01.y += n01.y; r23.x += n23.x; r23.y += n23.y;

    float4 sc0 = *reinterpret_cast<const float4*>(&g_scale[0][e]);
    float4 sc1 = *reinterpret_cast<const float4*>(&g_scale[1][e]);
    float4 b0  = *reinterpret_cast<const float4*>(&g_bias[0][e]);
    float4 b1  = *reinterpret_cast<const float4*>(&g_bias[1][e]);
    float fnl = (float)nl, fnr = (float)nr;
    float inv = 1.0f / fmaxf(fnl + fnr, 1.0f);

    float4 r;
    r.x = (l01.x * sc0.x + r01.x * sc1.x + fnl * b0.x + fnr * b1.x) * inv;
    r.y = (l01.y * sc0.y + r01.y * sc1.y + fnl * b0.y + fnr * b1.y) * inv;
    r.z = (l23.x * sc0.z + r23.x * sc1.z + fnl * b0.z + fnr * b1.z) * inv;
    r.w = (l23.y * sc0.w + r23.y * sc1.w + fnl * b0.w + fnr * b1.w) * inv;
    *reinterpret_cast<float4*>(out + (size_t)node * CE + off) = r;
}

extern "C" void kernel_launch(void* const* d_in, const int* in_sizes, int n_in,
                              void* d_out, int out_size) {
    const float* feat = (const float*)d_in[0];
    const float* dl   = (const float*)d_in[1];
    const float* dr   = (const float*)d_in[2];
    const float* lb   = (const float*)d_in[3];
    const float* rb   = (const float*)d_in[4];
    const int*   src  = (const int*)d_in[5];
    const int*   dst  = (const int*)d_in[6];
    const int*   pos  = (const int*)d_in[7];
    float* out = (float*)d_out;

    scatter_kernel<<<CONV_BLOCKS, 256>>>(feat, src, dst, pos, dl, dr, lb, rb);
    node_kernel<<<N_NODES, 64>>>(out);
}